// round 7
// baseline (speedup 1.0000x reference)
#include <cuda_runtime.h>
#include <cstdint>

#define SEQ   8192
#define DIM   256
#define HID   1024
#define KCB   512
#define NCLS  50
#define NCTA  128
#define TPB   256
#define UPC   8        // hidden units per CTA = HID / NCTA

// ---------------- device-global scratch (no allocations allowed) -------------
__device__ int      g_idx[SEQ];
__device__ float    g_hval[(SEQ + 1) * HID];        // h values, slot per step
__device__ unsigned g_flag[(SEQ + 1) * NCTA];       // per-CTA publish flag (gen)
// W_ih transposed+permuted: [k][cta*32 + r], r = gate*8 + unit. 8 MB.
__device__ float    g_wih_t[KCB * 4 * HID];
__device__ unsigned g_run = 0;   // generation counter, bumped once per launch

// ---------------- accurate-enough activations (fast-math independent) --------
__device__ __forceinline__ float sigm(float x) {
    return 1.0f / (1.0f + __expf(-x));
}
__device__ __forceinline__ float tanh_acc(float x) {
    float t = __expf(-2.0f * fabsf(x));
    float r = (1.0f - t) / (1.0f + t);
    return copysignf(r, x);
}

// packed f32x2 FMA (PTX-only pattern; element-wise fp32 FMA on a 64-bit pair)
__device__ __forceinline__ void ffma2(unsigned long long& d,
                                      unsigned long long a,
                                      unsigned long long b) {
    asm("fma.rn.f32x2 %0, %1, %2, %0;" : "+l"(d) : "l"(a), "l"(b));
}

__device__ __forceinline__ float4 ldcg_f4(const float4* p) {
    float4 v;
    asm volatile("ld.global.cg.v4.f32 {%0,%1,%2,%3}, [%4];"
                 : "=f"(v.x), "=f"(v.y), "=f"(v.z), "=f"(v.w)
                 : "l"(p) : "memory");
    return v;
}
__device__ __forceinline__ void stcg_f4(float4* p, float4 v) {
    asm volatile("st.global.cg.v4.f32 [%0], {%1,%2,%3,%4};"
                 :: "l"(p), "f"(v.x), "f"(v.y), "f"(v.z), "f"(v.w) : "memory");
}
__device__ __forceinline__ unsigned ld_relaxed(const unsigned* p) {
    unsigned v;
    asm volatile("ld.relaxed.gpu.global.u32 %0, [%1];" : "=r"(v) : "l"(p) : "memory");
    return v;
}
__device__ __forceinline__ void st_relaxed(unsigned* p, unsigned v) {
    asm volatile("st.relaxed.gpu.global.u32 [%0], %1;" :: "l"(p), "r"(v) : "memory");
}
__device__ __forceinline__ void fence_gpu() {
    asm volatile("fence.acq_rel.gpu;" ::: "memory");
}

// ======================= Kernel 1: VQ assignment (R3 config) =================
#define VQ_TOK  32
#define VQ_TILE 32
#define VQ_PAD  260
#define VQ_SMEM ((VQ_TOK * VQ_PAD + VQ_TILE * VQ_PAD) * sizeof(float))

__global__ __launch_bounds__(TPB)
void vq_kernel(const float* __restrict__ x, const float* __restrict__ cb) {
    extern __shared__ float sm[];
    float* sx  = sm;
    float* scb = sm + VQ_TOK * VQ_PAD;
    __shared__ float scn[KCB];

    const int tid = threadIdx.x;
    const int t0  = blockIdx.x * VQ_TOK;

    for (int i = tid; i < VQ_TOK * (DIM / 4); i += TPB) {
        int tt = i >> 6, d4 = i & 63;
        float4 v = *(const float4*)&x[(t0 + tt) * DIM + d4 * 4];
        *(float4*)&sx[tt * VQ_PAD + d4 * 4] = v;
    }
    for (int k = tid; k < KCB; k += TPB) {
        float s0 = 0.f, s1 = 0.f, s2 = 0.f, s3 = 0.f;
        const float4* cr = (const float4*)&cb[k * DIM];
        #pragma unroll 8
        for (int d = 0; d < DIM / 4; ++d) {
            float4 v = cr[d];
            s0 = fmaf(v.x, v.x, s0); s1 = fmaf(v.y, v.y, s1);
            s2 = fmaf(v.z, v.z, s2); s3 = fmaf(v.w, v.w, s3);
        }
        scn[k] = (s0 + s1) + (s2 + s3);
    }
    __syncthreads();

    const int tt = tid >> 3;
    const int k0 = tid & 7;
    float best = 3.4e38f;
    int   bidx = 0;

    for (int tile = 0; tile < KCB / VQ_TILE; ++tile) {
        for (int i = tid; i < VQ_TILE * (DIM / 4); i += TPB) {
            int cc = i >> 6, d4 = i & 63;
            float4 v = *(const float4*)&cb[(tile * VQ_TILE + cc) * DIM + d4 * 4];
            *(float4*)&scb[cc * VQ_PAD + d4 * 4] = v;
        }
        __syncthreads();
        for (int c = k0; c < VQ_TILE; c += 8) {
            float a0 = 0.f, a1 = 0.f, a2 = 0.f, a3 = 0.f;
            const float* xr = &sx[tt * VQ_PAD];
            const float* cr = &scb[c * VQ_PAD];
            #pragma unroll
            for (int d = 0; d < DIM; d += 4) {
                float4 xv = *(const float4*)&xr[d];
                float4 cv = *(const float4*)&cr[d];
                a0 = fmaf(xv.x, cv.x, a0); a1 = fmaf(xv.y, cv.y, a1);
                a2 = fmaf(xv.z, cv.z, a2); a3 = fmaf(xv.w, cv.w, a3);
            }
            int   kk   = tile * VQ_TILE + c;
            float dist = scn[kk] - 2.0f * ((a0 + a1) + (a2 + a3));
            if (dist < best) { best = dist; bidx = kk; }
        }
        __syncthreads();
    }
    #pragma unroll
    for (int off = 4; off > 0; off >>= 1) {
        float ob = __shfl_down_sync(0xffffffffu, best, off, 8);
        int   oi = __shfl_down_sync(0xffffffffu, bidx, off, 8);
        if (ob < best || (ob == best && oi < bidx)) { best = ob; bidx = oi; }
    }
    if (k0 == 0) g_idx[t0 + tt] = bidx;
}

// ======================= Kernel 1b: prep (R5 layout + gen bump) ==============
// g_wih_t[k*4096 + cta*32 + r] = W_ih[rowg(r,cta)*512 + k], rowg = g*1024+cta*8+u.
__global__ __launch_bounds__(256)
void prep_kernel(const float* __restrict__ W_ih) {
    int gid = blockIdx.x * 256 + threadIdx.x;       // 0 .. 512*4096-1
    if (gid == 0) g_run = g_run + 1;
    int k = gid >> 12;
    int c = gid & 4095;
    int r = c & 31, cta = c >> 5;
    int rowg = (r >> 3) * HID + cta * UPC + (r & 7);
    g_wih_t[gid] = __ldg(&W_ih[rowg * KCB + k]);
}

// ======================= Kernel 2: persistent data-flow LSTM =================
// R5 structure and BITWISE-IDENTICAL arithmetic. Only the h handoff changed:
// producers publish 8 values (lane-0 gathered, two st.cg.v4) then fence +
// one relaxed per-CTA flag; consumers poll ONLY flags (16 x 4B per warp per
// sweep -- 14x less L2 poll traffic than R5's data polling), then fence and
// load the values once, coalesced.
#define SH_STRIDE 36   // 32 + 4 pad floats -> conflict-free lane-strided reads

__global__ __launch_bounds__(TPB, 1)
void lstm_kernel(const float* __restrict__ h0,   const float* __restrict__ c0,
                 const float* __restrict__ W_hh,
                 const float* __restrict__ b_ih, const float* __restrict__ b_hh)
{
    __shared__ float sh[32 * SH_STRIDE];
    __shared__ float sg[32];
    __shared__ float sxp[32];
    __shared__ float sbias[32];
    __shared__ int   s_idx[2];

    const int tid  = threadIdx.x;
    const int b    = blockIdx.x;
    const int w    = tid >> 5;                // warp 0..7 -> rows 4w..4w+3
    const int l    = tid & 31;                // lane -> h slice [32l, 32l+32)
    const unsigned gen = g_run;

    // --- one-time: weights into registers as packed f32x2 pairs --------------
    unsigned long long wp[4][16];
    #pragma unroll
    for (int p = 0; p < 4; ++p) {
        int r    = 4 * w + p;
        int rowg = (r >> 3) * HID + b * UPC + (r & 7);
        const ulonglong2* wr = (const ulonglong2*)&W_hh[rowg * HID + l * 32];
        #pragma unroll
        for (int q = 0; q < 8; ++q) {
            ulonglong2 v = wr[q];
            wp[p][2 * q]     = v.x;
            wp[p][2 * q + 1] = v.y;
        }
    }
    if (tid < 32) {
        int rowg = (tid >> 3) * HID + b * UPC + (tid & 7);
        sbias[tid] = b_ih[rowg] + b_hh[rowg];
    }
    float c_state = 0.0f;
    if (tid < UPC) c_state = c0[b * UPC + tid];
    if (tid == 0)  s_idx[0] = g_idx[0];
    __syncthreads();

    for (int step = 1; step <= SEQ; ++step) {
        // ---- issue x-path loads early (R5 one-step-ahead idx pipeline) ------
        float4 xw4;
        if (tid < 8) {
            int idx = s_idx[(step - 1) & 1];
            xw4 = *(const float4*)&g_wih_t[idx * (4 * HID) + b * 32 + tid * 4];
        }
        if (tid == 8 && step < SEQ) s_idx[step & 1] = __ldg(&g_idx[step]);

        // ---- acquire h(step-1): flags first, then one-shot value load -------
        float4 hv;
        if (step == 1) {
            hv = *(const float4*)&h0[tid * 4];
        } else {
            const unsigned* fp = &g_flag[(step - 1) * NCTA + 16 * w + l];
            for (;;) {
                unsigned v = (l < 16) ? ld_relaxed(fp) : gen;
                if (__all_sync(0xffffffffu, v == gen)) break;
            }
            fence_gpu();
            hv = ldcg_f4((const float4*)&g_hval[(step - 1) * HID + tid * 4]);
        }
        *(float4*)&sh[(tid >> 3) * SH_STRIDE + (tid & 7) * 4] = hv;
        __syncthreads();

        // ---- register-resident GEMV (identical arithmetic to R5) ------------
        unsigned long long acc[4] = {0ull, 0ull, 0ull, 0ull};
        const ulonglong2* hp = (const ulonglong2*)&sh[l * SH_STRIDE];
        #pragma unroll
        for (int q = 0; q < 8; ++q) {
            ulonglong2 h2 = hp[q];
            #pragma unroll
            for (int p = 0; p < 4; ++p) {
                ffma2(acc[p], wp[p][2 * q],     h2.x);
                ffma2(acc[p], wp[p][2 * q + 1], h2.y);
            }
        }
        float accf[4];
        #pragma unroll
        for (int p = 0; p < 4; ++p) {
            float lo, hi;
            asm("mov.b64 {%0,%1}, %2;" : "=f"(lo), "=f"(hi) : "l"(acc[p]));
            accf[p] = lo + hi;
        }
        #pragma unroll
        for (int off = 16; off > 0; off >>= 1) {
            #pragma unroll
            for (int p = 0; p < 4; ++p)
                accf[p] += __shfl_down_sync(0xffffffffu, accf[p], off);
        }
        if (l == 0) {
            #pragma unroll
            for (int p = 0; p < 4; ++p) sg[4 * w + p] = accf[p];
        }
        if (tid < 8) *(float4*)&sxp[tid * 4] = xw4;
        __syncthreads();

        // ---- gates (R5 exact) + gathered publish + flag ---------------------
        if (tid < UPC) {
            int u = tid;
            float gi = sg[u]      + sxp[u]      + sbias[u];
            float gf = sg[8 + u]  + sxp[8 + u]  + sbias[8 + u];
            float gg = sg[16 + u] + sxp[16 + u] + sbias[16 + u];
            float go = sg[24 + u] + sxp[24 + u] + sbias[24 + u];
            float iv = sigm(gi), fv = sigm(gf);
            float gv = tanh_acc(gg), ov = sigm(go);
            c_state = fv * c_state + iv * gv;
            float hval = ov * tanh_acc(c_state);

            // gather 8 unit values to lane 0 (width-8 shuffle segment)
            float v1 = __shfl_sync(0xffu, hval, 1, 8);
            float v2 = __shfl_sync(0xffu, hval, 2, 8);
            float v3 = __shfl_sync(0xffu, hval, 3, 8);
            float v4 = __shfl_sync(0xffu, hval, 4, 8);
            float v5 = __shfl_sync(0xffu, hval, 5, 8);
            float v6 = __shfl_sync(0xffu, hval, 6, 8);
            float v7 = __shfl_sync(0xffu, hval, 7, 8);
            if (tid == 0) {
                float4* dst = (float4*)&g_hval[step * HID + b * UPC];
                stcg_f4(dst,     make_float4(hval, v1, v2, v3));
                stcg_f4(dst + 1, make_float4(v4,   v5, v6, v7));
                fence_gpu();
                st_relaxed(&g_flag[step * NCTA + b], gen);
            }
        }
    }
}

// ======================= Kernel 3: classifier head ===========================
__global__ __launch_bounds__(256)
void out_kernel(const float* __restrict__ W_out, const float* __restrict__ b_out,
                float* __restrict__ out)
{
    __shared__ float sl[NCLS];
    __shared__ float s_lse;
    const int tid = threadIdx.x, wp_ = tid >> 5, lane = tid & 31;

    for (int ll = wp_; ll < NCLS; ll += 8) {
        float s = 0.0f;
        #pragma unroll 8
        for (int j = lane; j < HID; j += 32) {
            float hv = g_hval[SEQ * HID + j];
            s = fmaf(hv, W_out[ll * HID + j], s);
        }
        #pragma unroll
        for (int off = 16; off > 0; off >>= 1)
            s += __shfl_down_sync(0xffffffffu, s, off);
        if (lane == 0) sl[ll] = s + b_out[ll];
    }
    __syncthreads();
    if (tid == 0) {
        float mx = -3.4e38f;
        for (int ll = 0; ll < NCLS; ++ll) mx = fmaxf(mx, sl[ll]);
        float se = 0.0f;
        for (int ll = 0; ll < NCLS; ++ll) se += __expf(sl[ll] - mx);
        s_lse = mx + __logf(se);
    }
    __syncthreads();
    if (tid < NCLS) out[tid] = sl[tid] - s_lse;
}

// ======================= launch ==============================================
extern "C" void kernel_launch(void* const* d_in, const int* in_sizes, int n_in,
                              void* d_out, int out_size) {
    const float* x     = (const float*)d_in[0];
    const float* h0    = (const float*)d_in[1];
    const float* c0    = (const float*)d_in[2];
    const float* cb    = (const float*)d_in[3];
    const float* W_ih  = (const float*)d_in[4];
    const float* W_hh  = (const float*)d_in[5];
    const float* b_ih  = (const float*)d_in[6];
    const float* b_hh  = (const float*)d_in[7];
    const float* W_out = (const float*)d_in[8];
    const float* b_out = (const float*)d_in[9];

    cudaFuncSetAttribute(vq_kernel, cudaFuncAttributeMaxDynamicSharedMemorySize,
                         (int)VQ_SMEM);

    vq_kernel<<<SEQ / VQ_TOK, TPB, VQ_SMEM>>>(x, cb);
    prep_kernel<<<(KCB * 4 * HID) / 256, 256>>>(W_ih);
    lstm_kernel<<<NCTA, TPB>>>(h0, c0, W_hh, b_ih, b_hh);
    out_kernel<<<1, 256>>>(W_out, b_out, (float*)d_out);
}

// round 8
// speedup vs baseline: 2.6050x; 2.6050x over previous
#include <cuda_runtime.h>
#include <cstdint>

#define SEQ   8192
#define DIM   256
#define HID   1024
#define KCB   512
#define NCLS  50
#define NCTA  128
#define TPB   256
#define UPC   8        // hidden units per CTA = HID / NCTA

// ---------------- device-global scratch (no allocations allowed) -------------
__device__ int      g_idx[SEQ];
// h publish buffer: slot s holds h(s); one u64 {gen:hi32, val:lo32} per unit.
// 8-byte relaxed accesses are single-copy atomic -> tag self-validates value.
__device__ unsigned long long g_hpub[(SEQ + 1) * HID];
// W_ih transposed+permuted: [k][cta*32 + r], r = gate*8 + unit. 8 MB.
__device__ float    g_wih_t[KCB * 4 * HID];
__device__ unsigned g_run = 0;   // generation counter, bumped once per launch

// ---------------- accurate-enough activations (fast-math independent) --------
__device__ __forceinline__ float sigm(float x) {
    return 1.0f / (1.0f + __expf(-x));
}
__device__ __forceinline__ float tanh_acc(float x) {
    float t = __expf(-2.0f * fabsf(x));
    float r = (1.0f - t) / (1.0f + t);
    return copysignf(r, x);
}

// packed f32x2 FMA (PTX-only pattern; element-wise fp32 FMA on a 64-bit pair)
__device__ __forceinline__ void ffma2(unsigned long long& d,
                                      unsigned long long a,
                                      unsigned long long b) {
    asm("fma.rn.f32x2 %0, %1, %2, %0;" : "+l"(d) : "l"(a), "l"(b));
}

// 8-byte single-copy-atomic publish/poll primitives (L2-visible, no L1 staleness)
__device__ __forceinline__ unsigned long long ldrel64(const unsigned long long* p) {
    unsigned long long v;
    asm volatile("ld.relaxed.gpu.global.u64 %0, [%1];" : "=l"(v) : "l"(p) : "memory");
    return v;
}
__device__ __forceinline__ void strel64(unsigned long long* p, unsigned long long v) {
    asm volatile("st.relaxed.gpu.global.u64 [%0], %1;" :: "l"(p), "l"(v) : "memory");
}

// ======================= Kernel 1: VQ assignment (R5 exact) ==================
#define VQ_TOK  32
#define VQ_TILE 32
#define VQ_PAD  260
#define VQ_SMEM ((VQ_TOK * VQ_PAD + VQ_TILE * VQ_PAD) * sizeof(float))

__global__ __launch_bounds__(TPB)
void vq_kernel(const float* __restrict__ x, const float* __restrict__ cb) {
    extern __shared__ float sm[];
    float* sx  = sm;
    float* scb = sm + VQ_TOK * VQ_PAD;
    __shared__ float scn[KCB];

    const int tid = threadIdx.x;
    const int t0  = blockIdx.x * VQ_TOK;

    for (int i = tid; i < VQ_TOK * (DIM / 4); i += TPB) {
        int tt = i >> 6, d4 = i & 63;
        float4 v = *(const float4*)&x[(t0 + tt) * DIM + d4 * 4];
        *(float4*)&sx[tt * VQ_PAD + d4 * 4] = v;
    }
    for (int k = tid; k < KCB; k += TPB) {
        float s0 = 0.f, s1 = 0.f, s2 = 0.f, s3 = 0.f;
        const float4* cr = (const float4*)&cb[k * DIM];
        #pragma unroll 8
        for (int d = 0; d < DIM / 4; ++d) {
            float4 v = cr[d];
            s0 = fmaf(v.x, v.x, s0); s1 = fmaf(v.y, v.y, s1);
            s2 = fmaf(v.z, v.z, s2); s3 = fmaf(v.w, v.w, s3);
        }
        scn[k] = (s0 + s1) + (s2 + s3);
    }
    __syncthreads();

    const int tt = tid >> 3;
    const int k0 = tid & 7;
    float best = 3.4e38f;
    int   bidx = 0;

    for (int tile = 0; tile < KCB / VQ_TILE; ++tile) {
        for (int i = tid; i < VQ_TILE * (DIM / 4); i += TPB) {
            int cc = i >> 6, d4 = i & 63;
            float4 v = *(const float4*)&cb[(tile * VQ_TILE + cc) * DIM + d4 * 4];
            *(float4*)&scb[cc * VQ_PAD + d4 * 4] = v;
        }
        __syncthreads();
        for (int c = k0; c < VQ_TILE; c += 8) {
            float a0 = 0.f, a1 = 0.f, a2 = 0.f, a3 = 0.f;
            const float* xr = &sx[tt * VQ_PAD];
            const float* cr = &scb[c * VQ_PAD];
            #pragma unroll
            for (int d = 0; d < DIM; d += 4) {
                float4 xv = *(const float4*)&xr[d];
                float4 cv = *(const float4*)&cr[d];
                a0 = fmaf(xv.x, cv.x, a0); a1 = fmaf(xv.y, cv.y, a1);
                a2 = fmaf(xv.z, cv.z, a2); a3 = fmaf(xv.w, cv.w, a3);
            }
            int   kk   = tile * VQ_TILE + c;
            float dist = scn[kk] - 2.0f * ((a0 + a1) + (a2 + a3));
            if (dist < best) { best = dist; bidx = kk; }
        }
        __syncthreads();
    }
    #pragma unroll
    for (int off = 4; off > 0; off >>= 1) {
        float ob = __shfl_down_sync(0xffffffffu, best, off, 8);
        int   oi = __shfl_down_sync(0xffffffffu, bidx, off, 8);
        if (ob < best || (ob == best && oi < bidx)) { best = ob; bidx = oi; }
    }
    if (k0 == 0) g_idx[t0 + tt] = bidx;
}

// ======================= Kernel 1b: prep (R5 layout + gen bump) ==============
__global__ __launch_bounds__(256)
void prep_kernel(const float* __restrict__ W_ih) {
    int gid = blockIdx.x * 256 + threadIdx.x;       // 0 .. 512*4096-1
    if (gid == 0) g_run = g_run + 1;
    int k = gid >> 12;
    int c = gid & 4095;
    int r = c & 31, cta = c >> 5;
    int rowg = (r >> 3) * HID + cta * UPC + (r & 7);
    g_wih_t[gid] = __ldg(&W_ih[rowg * KCB + k]);
}

// ======================= Kernel 2: persistent data-flow LSTM =================
// R5 structure, bitwise-identical arithmetic. Handoff fixed: each unit's
// {gen,val} published as ONE 8-byte st.relaxed.gpu (single-copy atomic, no
// fence, no torn tag/value). Consumers poll 4x 8-byte relaxed loads per
// thread (same 32B footprint and coalescing as the 11.1ms R5 kernel),
// pipelined 2-deep to halve the effective sampling period.
#define SH_STRIDE 36   // 32 + 4 pad floats -> conflict-free lane-strided reads

__global__ __launch_bounds__(TPB, 1)
void lstm_kernel(const float* __restrict__ h0,   const float* __restrict__ c0,
                 const float* __restrict__ W_hh,
                 const float* __restrict__ b_ih, const float* __restrict__ b_hh)
{
    __shared__ float sh[32 * SH_STRIDE];
    __shared__ float sg[32];
    __shared__ float sxp[32];
    __shared__ float sbias[32];
    __shared__ int   s_idx[2];

    const int tid  = threadIdx.x;
    const int b    = blockIdx.x;
    const int w    = tid >> 5;                // warp 0..7 -> rows 4w..4w+3
    const int l    = tid & 31;                // lane -> h slice [32l, 32l+32)
    const unsigned gen = g_run;
    const unsigned long long want = ((unsigned long long)gen) << 32;

    // --- one-time: weights into registers as packed f32x2 pairs --------------
    unsigned long long wp[4][16];
    #pragma unroll
    for (int p = 0; p < 4; ++p) {
        int r    = 4 * w + p;
        int rowg = (r >> 3) * HID + b * UPC + (r & 7);
        const ulonglong2* wr = (const ulonglong2*)&W_hh[rowg * HID + l * 32];
        #pragma unroll
        for (int q = 0; q < 8; ++q) {
            ulonglong2 v = wr[q];
            wp[p][2 * q]     = v.x;
            wp[p][2 * q + 1] = v.y;
        }
    }
    if (tid < 32) {
        int rowg = (tid >> 3) * HID + b * UPC + (tid & 7);
        sbias[tid] = b_ih[rowg] + b_hh[rowg];
    }
    float c_state = 0.0f;
    if (tid < UPC) c_state = c0[b * UPC + tid];
    if (tid == 0)  s_idx[0] = g_idx[0];
    __syncthreads();

    for (int step = 1; step <= SEQ; ++step) {
        // ---- issue x-path loads early (one-step-ahead idx pipeline) ---------
        float4 xw4;
        if (tid < 8) {
            int idx = s_idx[(step - 1) & 1];
            xw4 = *(const float4*)&g_wih_t[idx * (4 * HID) + b * 32 + tid * 4];
        }
        if (tid == 8 && step < SEQ) s_idx[step & 1] = __ldg(&g_idx[step]);

        // ---- acquire h(step-1): pipelined poll on self-validating words -----
        float4 hv;
        if (step == 1) {
            hv = *(const float4*)&h0[tid * 4];
        } else {
            const unsigned long long* pp = &g_hpub[(step - 1) * HID + tid * 4];
            unsigned long long a0 = ldrel64(pp),     a1 = ldrel64(pp + 1);
            unsigned long long a2 = ldrel64(pp + 2), a3 = ldrel64(pp + 3);
            for (;;) {
                // issue next sample before checking the current one
                unsigned long long b0 = ldrel64(pp),     b1 = ldrel64(pp + 1);
                unsigned long long b2 = ldrel64(pp + 2), b3 = ldrel64(pp + 3);
                if ((((a0 ^ want) | (a1 ^ want) |
                      (a2 ^ want) | (a3 ^ want)) >> 32) == 0ull) break;
                unsigned long long c0_ = ldrel64(pp),     c1 = ldrel64(pp + 1);
                unsigned long long c2 = ldrel64(pp + 2), c3 = ldrel64(pp + 3);
                if ((((b0 ^ want) | (b1 ^ want) |
                      (b2 ^ want) | (b3 ^ want)) >> 32) == 0ull) {
                    a0 = b0; a1 = b1; a2 = b2; a3 = b3; break;
                }
                a0 = c0_; a1 = c1; a2 = c2; a3 = c3;
            }
            hv.x = __uint_as_float((unsigned)a0);
            hv.y = __uint_as_float((unsigned)a1);
            hv.z = __uint_as_float((unsigned)a2);
            hv.w = __uint_as_float((unsigned)a3);
        }
        *(float4*)&sh[(tid >> 3) * SH_STRIDE + (tid & 7) * 4] = hv;
        __syncthreads();

        // ---- register-resident GEMV (identical arithmetic to R5) ------------
        unsigned long long acc[4] = {0ull, 0ull, 0ull, 0ull};
        const ulonglong2* hp = (const ulonglong2*)&sh[l * SH_STRIDE];
        #pragma unroll
        for (int q = 0; q < 8; ++q) {
            ulonglong2 h2 = hp[q];
            #pragma unroll
            for (int p = 0; p < 4; ++p) {
                ffma2(acc[p], wp[p][2 * q],     h2.x);
                ffma2(acc[p], wp[p][2 * q + 1], h2.y);
            }
        }
        float accf[4];
        #pragma unroll
        for (int p = 0; p < 4; ++p) {
            float lo, hi;
            asm("mov.b64 {%0,%1}, %2;" : "=f"(lo), "=f"(hi) : "l"(acc[p]));
            accf[p] = lo + hi;
        }
        #pragma unroll
        for (int off = 16; off > 0; off >>= 1) {
            #pragma unroll
            for (int p = 0; p < 4; ++p)
                accf[p] += __shfl_down_sync(0xffffffffu, accf[p], off);
        }
        if (l == 0) {
            #pragma unroll
            for (int p = 0; p < 4; ++p) sg[4 * w + p] = accf[p];
        }
        if (tid < 8) *(float4*)&sxp[tid * 4] = xw4;
        __syncthreads();

        // ---- gates (R5 exact) + atomic 8B publish ---------------------------
        if (tid < UPC) {
            int u = tid;
            float gi = sg[u]      + sxp[u]      + sbias[u];
            float gf = sg[8 + u]  + sxp[8 + u]  + sbias[8 + u];
            float gg = sg[16 + u] + sxp[16 + u] + sbias[16 + u];
            float go = sg[24 + u] + sxp[24 + u] + sbias[24 + u];
            float iv = sigm(gi), fv = sigm(gf);
            float gv = tanh_acc(gg), ov = sigm(go);
            c_state = fv * c_state + iv * gv;
            float hval = ov * tanh_acc(c_state);
            unsigned long long rec =
                want | (unsigned long long)__float_as_uint(hval);
            strel64(&g_hpub[step * HID + b * UPC + u], rec);
        }
    }
}

// ======================= Kernel 3: classifier head ===========================
__global__ __launch_bounds__(256)
void out_kernel(const float* __restrict__ W_out, const float* __restrict__ b_out,
                float* __restrict__ out)
{
    __shared__ float sl[NCLS];
    __shared__ float s_lse;
    const int tid = threadIdx.x, wp_ = tid >> 5, lane = tid & 31;

    for (int ll = wp_; ll < NCLS; ll += 8) {
        float s = 0.0f;
        #pragma unroll 8
        for (int j = lane; j < HID; j += 32) {
            float hv = __uint_as_float((unsigned)g_hpub[SEQ * HID + j]);
            s = fmaf(hv, W_out[ll * HID + j], s);
        }
        #pragma unroll
        for (int off = 16; off > 0; off >>= 1)
            s += __shfl_down_sync(0xffffffffu, s, off);
        if (lane == 0) sl[ll] = s + b_out[ll];
    }
    __syncthreads();
    if (tid == 0) {
        float mx = -3.4e38f;
        for (int ll = 0; ll < NCLS; ++ll) mx = fmaxf(mx, sl[ll]);
        float se = 0.0f;
        for (int ll = 0; ll < NCLS; ++ll) se += __expf(sl[ll] - mx);
        s_lse = mx + __logf(se);
    }
    __syncthreads();
    if (tid < NCLS) out[tid] = sl[tid] - s_lse;
}

// ======================= launch ==============================================
extern "C" void kernel_launch(void* const* d_in, const int* in_sizes, int n_in,
                              void* d_out, int out_size) {
    const float* x     = (const float*)d_in[0];
    const float* h0    = (const float*)d_in[1];
    const float* c0    = (const float*)d_in[2];
    const float* cb    = (const float*)d_in[3];
    const float* W_ih  = (const float*)d_in[4];
    const float* W_hh  = (const float*)d_in[5];
    const float* b_ih  = (const float*)d_in[6];
    const float* b_hh  = (const float*)d_in[7];
    const float* W_out = (const float*)d_in[8];
    const float* b_out = (const float*)d_in[9];

    cudaFuncSetAttribute(vq_kernel, cudaFuncAttributeMaxDynamicSharedMemorySize,
                         (int)VQ_SMEM);

    vq_kernel<<<SEQ / VQ_TOK, TPB, VQ_SMEM>>>(x, cb);
    prep_kernel<<<(KCB * 4 * HID) / 256, 256>>>(W_ih);
    lstm_kernel<<<NCTA, TPB>>>(h0, c0, W_hh, b_ih, b_hh);
    out_kernel<<<1, 256>>>(W_out, b_out, (float*)d_out);
}

// round 9
// speedup vs baseline: 7.3021x; 2.8031x over previous
#include <cuda_runtime.h>
#include <cstdint>

#define SEQ   8192
#define DIM   256
#define HID   1024
#define KCB   512
#define NCLS  50
#define NCTA  128
#define TPB   256
#define UPC   8        // hidden units per CTA = HID / NCTA

// ---------------- device-global scratch (no allocations allowed) -------------
__device__ int      g_idx[SEQ];
// h publish buffer: slot s holds h(s); one u64 {gen:hi32, val:lo32} per unit.
// PRODUCER side uses st.relaxed.gpu.u64 -> the 8B record commits atomically
// (no torn tag/value, the R5/R6 race). CONSUMER side polls with fast weak
// ld.global.cg.v4 (one 16B L2 access covering two self-validating records).
__device__ unsigned long long g_hpub[(SEQ + 1) * HID];
// W_ih transposed+permuted: [k][cta*32 + r], r = gate*8 + unit. 8 MB.
__device__ float    g_wih_t[KCB * 4 * HID];
__device__ unsigned g_run = 0;   // generation counter, bumped once per launch

// ---------------- accurate-enough activations (fast-math independent) --------
__device__ __forceinline__ float sigm(float x) {
    return 1.0f / (1.0f + __expf(-x));
}
__device__ __forceinline__ float tanh_acc(float x) {
    float t = __expf(-2.0f * fabsf(x));
    float r = (1.0f - t) / (1.0f + t);
    return copysignf(r, x);
}

// packed f32x2 FMA (PTX-only pattern; element-wise fp32 FMA on a 64-bit pair)
__device__ __forceinline__ void ffma2(unsigned long long& d,
                                      unsigned long long a,
                                      unsigned long long b) {
    asm("fma.rn.f32x2 %0, %1, %2, %0;" : "+l"(d) : "l"(a), "l"(b));
}

__device__ __forceinline__ uint4 ldcg_u4(const uint4* p) {
    uint4 v;
    asm volatile("ld.global.cg.v4.u32 {%0,%1,%2,%3}, [%4];"
                 : "=r"(v.x), "=r"(v.y), "=r"(v.z), "=r"(v.w)
                 : "l"(p) : "memory");
    return v;
}
__device__ __forceinline__ void strel64(unsigned long long* p, unsigned long long v) {
    asm volatile("st.relaxed.gpu.global.u64 [%0], %1;" :: "l"(p), "l"(v) : "memory");
}

// ======================= Kernel 1: VQ assignment (R5 exact) ==================
#define VQ_TOK  32
#define VQ_TILE 32
#define VQ_PAD  260
#define VQ_SMEM ((VQ_TOK * VQ_PAD + VQ_TILE * VQ_PAD) * sizeof(float))

__global__ __launch_bounds__(TPB)
void vq_kernel(const float* __restrict__ x, const float* __restrict__ cb) {
    extern __shared__ float sm[];
    float* sx  = sm;
    float* scb = sm + VQ_TOK * VQ_PAD;
    __shared__ float scn[KCB];

    const int tid = threadIdx.x;
    const int t0  = blockIdx.x * VQ_TOK;

    for (int i = tid; i < VQ_TOK * (DIM / 4); i += TPB) {
        int tt = i >> 6, d4 = i & 63;
        float4 v = *(const float4*)&x[(t0 + tt) * DIM + d4 * 4];
        *(float4*)&sx[tt * VQ_PAD + d4 * 4] = v;
    }
    for (int k = tid; k < KCB; k += TPB) {
        float s0 = 0.f, s1 = 0.f, s2 = 0.f, s3 = 0.f;
        const float4* cr = (const float4*)&cb[k * DIM];
        #pragma unroll 8
        for (int d = 0; d < DIM / 4; ++d) {
            float4 v = cr[d];
            s0 = fmaf(v.x, v.x, s0); s1 = fmaf(v.y, v.y, s1);
            s2 = fmaf(v.z, v.z, s2); s3 = fmaf(v.w, v.w, s3);
        }
        scn[k] = (s0 + s1) + (s2 + s3);
    }
    __syncthreads();

    const int tt = tid >> 3;
    const int k0 = tid & 7;
    float best = 3.4e38f;
    int   bidx = 0;

    for (int tile = 0; tile < KCB / VQ_TILE; ++tile) {
        for (int i = tid; i < VQ_TILE * (DIM / 4); i += TPB) {
            int cc = i >> 6, d4 = i & 63;
            float4 v = *(const float4*)&cb[(tile * VQ_TILE + cc) * DIM + d4 * 4];
            *(float4*)&scb[cc * VQ_PAD + d4 * 4] = v;
        }
        __syncthreads();
        for (int c = k0; c < VQ_TILE; c += 8) {
            float a0 = 0.f, a1 = 0.f, a2 = 0.f, a3 = 0.f;
            const float* xr = &sx[tt * VQ_PAD];
            const float* cr = &scb[c * VQ_PAD];
            #pragma unroll
            for (int d = 0; d < DIM; d += 4) {
                float4 xv = *(const float4*)&xr[d];
                float4 cv = *(const float4*)&cr[d];
                a0 = fmaf(xv.x, cv.x, a0); a1 = fmaf(xv.y, cv.y, a1);
                a2 = fmaf(xv.z, cv.z, a2); a3 = fmaf(xv.w, cv.w, a3);
            }
            int   kk   = tile * VQ_TILE + c;
            float dist = scn[kk] - 2.0f * ((a0 + a1) + (a2 + a3));
            if (dist < best) { best = dist; bidx = kk; }
        }
        __syncthreads();
    }
    #pragma unroll
    for (int off = 4; off > 0; off >>= 1) {
        float ob = __shfl_down_sync(0xffffffffu, best, off, 8);
        int   oi = __shfl_down_sync(0xffffffffu, bidx, off, 8);
        if (ob < best || (ob == best && oi < bidx)) { best = ob; bidx = oi; }
    }
    if (k0 == 0) g_idx[t0 + tt] = bidx;
}

// ======================= Kernel 1b: prep (R5 layout + gen bump) ==============
__global__ __launch_bounds__(256)
void prep_kernel(const float* __restrict__ W_ih) {
    int gid = blockIdx.x * 256 + threadIdx.x;       // 0 .. 512*4096-1
    if (gid == 0) g_run = g_run + 1;
    int k = gid >> 12;
    int c = gid & 4095;
    int r = c & 31, cta = c >> 5;
    int rowg = (r >> 3) * HID + cta * UPC + (r & 7);
    g_wih_t[gid] = __ldg(&W_ih[rowg * KCB + k]);
}

// ======================= Kernel 2: persistent data-flow LSTM =================
// R5 structure, bitwise-identical arithmetic. Publish: one atomic 8B strong
// store per unit (tag+value in one word). Poll: R5's weak cg v4 loads (two
// records per load, tag checked per record), pipelined 2-deep.
#define SH_STRIDE 36   // 32 + 4 pad floats -> conflict-free lane-strided reads

__global__ __launch_bounds__(TPB, 1)
void lstm_kernel(const float* __restrict__ h0,   const float* __restrict__ c0,
                 const float* __restrict__ W_hh,
                 const float* __restrict__ b_ih, const float* __restrict__ b_hh)
{
    __shared__ float sh[32 * SH_STRIDE];
    __shared__ float sg[32];
    __shared__ float sxp[32];
    __shared__ float sbias[32];
    __shared__ int   s_idx[2];

    const int tid  = threadIdx.x;
    const int b    = blockIdx.x;
    const int w    = tid >> 5;                // warp 0..7 -> rows 4w..4w+3
    const int l    = tid & 31;                // lane -> h slice [32l, 32l+32)
    const unsigned gen = g_run;
    const unsigned long long want = ((unsigned long long)gen) << 32;

    // --- one-time: weights into registers as packed f32x2 pairs --------------
    unsigned long long wp[4][16];
    #pragma unroll
    for (int p = 0; p < 4; ++p) {
        int r    = 4 * w + p;
        int rowg = (r >> 3) * HID + b * UPC + (r & 7);
        const ulonglong2* wr = (const ulonglong2*)&W_hh[rowg * HID + l * 32];
        #pragma unroll
        for (int q = 0; q < 8; ++q) {
            ulonglong2 v = wr[q];
            wp[p][2 * q]     = v.x;
            wp[p][2 * q + 1] = v.y;
        }
    }
    if (tid < 32) {
        int rowg = (tid >> 3) * HID + b * UPC + (tid & 7);
        sbias[tid] = b_ih[rowg] + b_hh[rowg];
    }
    float c_state = 0.0f;
    if (tid < UPC) c_state = c0[b * UPC + tid];
    if (tid == 0)  s_idx[0] = g_idx[0];
    __syncthreads();

    for (int step = 1; step <= SEQ; ++step) {
        // ---- issue x-path loads early (one-step-ahead idx pipeline) ---------
        float4 xw4;
        if (tid < 8) {
            int idx = s_idx[(step - 1) & 1];
            xw4 = *(const float4*)&g_wih_t[idx * (4 * HID) + b * 32 + tid * 4];
        }
        if (tid == 8 && step < SEQ) s_idx[step & 1] = __ldg(&g_idx[step]);

        // ---- acquire h(step-1): pipelined weak-cg poll, tag per 8B record ---
        float4 hv;
        if (step == 1) {
            hv = *(const float4*)&h0[tid * 4];
        } else {
            const uint4* pa = (const uint4*)&g_hpub[(step - 1) * HID + tid * 4];
            uint4 A = ldcg_u4(pa), B = ldcg_u4(pa + 1);
            for (;;) {
                if ((((A.y ^ gen) | (A.w ^ gen)) |
                     ((B.y ^ gen) | (B.w ^ gen))) == 0u) break;
                // issue next sample, re-check it (pipelined: one load latency
                // per failed sample instead of two)
                uint4 A2 = ldcg_u4(pa), B2 = ldcg_u4(pa + 1);
                A = A2; B = B2;
            }
            hv.x = __uint_as_float(A.x); hv.y = __uint_as_float(A.z);
            hv.z = __uint_as_float(B.x); hv.w = __uint_as_float(B.z);
        }
        *(float4*)&sh[(tid >> 3) * SH_STRIDE + (tid & 7) * 4] = hv;
        __syncthreads();

        // ---- register-resident GEMV (identical arithmetic to R5) ------------
        unsigned long long acc[4] = {0ull, 0ull, 0ull, 0ull};
        const ulonglong2* hp = (const ulonglong2*)&sh[l * SH_STRIDE];
        #pragma unroll
        for (int q = 0; q < 8; ++q) {
            ulonglong2 h2 = hp[q];
            #pragma unroll
            for (int p = 0; p < 4; ++p) {
                ffma2(acc[p], wp[p][2 * q],     h2.x);
                ffma2(acc[p], wp[p][2 * q + 1], h2.y);
            }
        }
        float accf[4];
        #pragma unroll
        for (int p = 0; p < 4; ++p) {
            float lo, hi;
            asm("mov.b64 {%0,%1}, %2;" : "=f"(lo), "=f"(hi) : "l"(acc[p]));
            accf[p] = lo + hi;
        }
        #pragma unroll
        for (int off = 16; off > 0; off >>= 1) {
            #pragma unroll
            for (int p = 0; p < 4; ++p)
                accf[p] += __shfl_down_sync(0xffffffffu, accf[p], off);
        }
        if (l == 0) {
            #pragma unroll
            for (int p = 0; p < 4; ++p) sg[4 * w + p] = accf[p];
        }
        if (tid < 8) *(float4*)&sxp[tid * 4] = xw4;
        __syncthreads();

        // ---- gates (R5 exact) + atomic 8B publish ---------------------------
        if (tid < UPC) {
            int u = tid;
            float gi = sg[u]      + sxp[u]      + sbias[u];
            float gf = sg[8 + u]  + sxp[8 + u]  + sbias[8 + u];
            float gg = sg[16 + u] + sxp[16 + u] + sbias[16 + u];
            float go = sg[24 + u] + sxp[24 + u] + sbias[24 + u];
            float iv = sigm(gi), fv = sigm(gf);
            float gv = tanh_acc(gg), ov = sigm(go);
            c_state = fv * c_state + iv * gv;
            float hval = ov * tanh_acc(c_state);
            unsigned long long rec =
                want | (unsigned long long)__float_as_uint(hval);
            strel64(&g_hpub[step * HID + b * UPC + u], rec);
        }
    }
}

// ======================= Kernel 3: classifier head ===========================
__global__ __launch_bounds__(256)
void out_kernel(const float* __restrict__ W_out, const float* __restrict__ b_out,
                float* __restrict__ out)
{
    __shared__ float sl[NCLS];
    __shared__ float s_lse;
    const int tid = threadIdx.x, wp_ = tid >> 5, lane = tid & 31;

    for (int ll = wp_; ll < NCLS; ll += 8) {
        float s = 0.0f;
        #pragma unroll 8
        for (int j = lane; j < HID; j += 32) {
            float hv = __uint_as_float((unsigned)g_hpub[SEQ * HID + j]);
            s = fmaf(hv, W_out[ll * HID + j], s);
        }
        #pragma unroll
        for (int off = 16; off > 0; off >>= 1)
            s += __shfl_down_sync(0xffffffffu, s, off);
        if (lane == 0) sl[ll] = s + b_out[ll];
    }
    __syncthreads();
    if (tid == 0) {
        float mx = -3.4e38f;
        for (int ll = 0; ll < NCLS; ++ll) mx = fmaxf(mx, sl[ll]);
        float se = 0.0f;
        for (int ll = 0; ll < NCLS; ++ll) se += __expf(sl[ll] - mx);
        s_lse = mx + __logf(se);
    }
    __syncthreads();
    if (tid < NCLS) out[tid] = sl[tid] - s_lse;
}

// ======================= launch ==============================================
extern "C" void kernel_launch(void* const* d_in, const int* in_sizes, int n_in,
                              void* d_out, int out_size) {
    const float* x     = (const float*)d_in[0];
    const float* h0    = (const float*)d_in[1];
    const float* c0    = (const float*)d_in[2];
    const float* cb    = (const float*)d_in[3];
    const float* W_ih  = (const float*)d_in[4];
    const float* W_hh  = (const float*)d_in[5];
    const float* b_ih  = (const float*)d_in[6];
    const float* b_hh  = (const float*)d_in[7];
    const float* W_out = (const float*)d_in[8];
    const float* b_out = (const float*)d_in[9];

    cudaFuncSetAttribute(vq_kernel, cudaFuncAttributeMaxDynamicSharedMemorySize,
                         (int)VQ_SMEM);

    vq_kernel<<<SEQ / VQ_TOK, TPB, VQ_SMEM>>>(x, cb);
    prep_kernel<<<(KCB * 4 * HID) / 256, 256>>>(W_ih);
    lstm_kernel<<<NCTA, TPB>>>(h0, c0, W_hh, b_ih, b_hh);
    out_kernel<<<1, 256>>>(W_out, b_out, (float*)d_out);
}